// round 2
// baseline (speedup 1.0000x reference)
#include <cuda_runtime.h>
#include <cstdint>

// Problem constants
#define NN      8192
#define CH      16
#define KT      512            // k-chunk staged in shared
#define RS      1028           // padded row stride (float words) per channel-pair row (2*KT + 4)
#define RPW     4              // rows per warp
#define WPC     8              // warps per CTA
#define RPC     32             // rows per CTA
#define THREADS 256
#define NCTA    (NN / RPC)     // 256

// Scratch (no allocation allowed): ping-pong xp buffers + accumulator
__device__ __align__(128) float g_xbuf0[NN * CH];
__device__ __align__(128) float g_xbuf1[NN * CH];
__device__ __align__(128) float g_acc[NN * CH];

// ---------------- packed f32x2 helpers ----------------
__device__ __forceinline__ unsigned long long f2_fma(unsigned long long a,
                                                     unsigned long long b,
                                                     unsigned long long c) {
    unsigned long long d;
    asm("fma.rn.f32x2 %0, %1, %2, %3;" : "=l"(d) : "l"(a), "l"(b), "l"(c));
    return d;
}
__device__ __forceinline__ unsigned long long f2_add(unsigned long long a,
                                                     unsigned long long b) {
    unsigned long long d;
    asm("add.rn.f32x2 %0, %1, %2;" : "=l"(d) : "l"(a), "l"(b));
    return d;
}
__device__ __forceinline__ unsigned long long f2_pack(float lo, float hi) {
    unsigned long long d;
    asm("mov.b64 %0, {%1, %2};" : "=l"(d) : "f"(lo), "f"(hi));
    return d;
}
__device__ __forceinline__ void f2_unpack(unsigned long long v, float& lo, float& hi) {
    asm("mov.b64 {%0, %1}, %2;" : "=f"(lo), "=f"(hi) : "l"(v));
}

// ---------------- kernel 0: acc = relu(x @ W0) ----------------
__global__ void k_init(const float* __restrict__ x,
                       const float* __restrict__ W,   // W0: [16][16]
                       float* __restrict__ acc) {
    __shared__ float sW[CH * CH];
    int t = threadIdx.x;
    sW[t] = W[t];
    __syncthreads();

    int row = blockIdx.x * blockDim.x + t;   // grid = 32 blocks of 256
    const float4* xr4 = reinterpret_cast<const float4*>(x + (size_t)row * CH);
    float xr[CH];
    float4 v0 = xr4[0], v1 = xr4[1], v2 = xr4[2], v3 = xr4[3];
    xr[0]=v0.x; xr[1]=v0.y; xr[2]=v0.z; xr[3]=v0.w;
    xr[4]=v1.x; xr[5]=v1.y; xr[6]=v1.z; xr[7]=v1.w;
    xr[8]=v2.x; xr[9]=v2.y; xr[10]=v2.z; xr[11]=v2.w;
    xr[12]=v3.x; xr[13]=v3.y; xr[14]=v3.z; xr[15]=v3.w;

    float o[CH];
    #pragma unroll
    for (int c = 0; c < CH; c++) o[c] = 0.f;
    #pragma unroll
    for (int j = 0; j < CH; j++) {
        #pragma unroll
        for (int c = 0; c < CH; c++) o[c] += xr[j] * sW[j * CH + c];
    }
    float* ar = acc + (size_t)row * CH;
    #pragma unroll
    for (int c = 0; c < CH; c++) ar[c] = fmaxf(o[c], 0.f);
}

// ---------------- pass kernel: y = L @ xin ; acc += relu(y @ Wp) ; xout = y ----------------
// FINAL: out = relu(acc + relu(y @ Wp)), no xout write.
template <bool FINAL>
__global__ __launch_bounds__(THREADS, 2)
void k_pass(const float* __restrict__ L,
            const float* __restrict__ xin,
            float* __restrict__ xout,
            const float* __restrict__ W,      // Wp: [16][16]
            float* __restrict__ acc,
            float* __restrict__ outp) {
    // Channel-pair-major transposed xp chunk: sxp[c2*RS + 2*k + j] = xp[k][2*c2 + j]
    __shared__ __align__(16) float sxp[8 * RS];
    __shared__ float sW[CH * CH];

    int t = threadIdx.x;
    sW[t] = W[t];

    int warp = t >> 5;
    int lane = t & 31;
    int rowbase = blockIdx.x * RPC + warp * RPW;
    const float* Lr = L + (size_t)rowbase * NN;

    unsigned long long acc2[RPW][8];
    #pragma unroll
    for (int r = 0; r < RPW; r++)
        #pragma unroll
        for (int c2 = 0; c2 < 8; c2++) acc2[r][c2] = 0ull;

    for (int chunk = 0; chunk < NN / KT; ++chunk) {   // 16 chunks
        // ---- stage xp[chunk*KT .. +KT)[16] into pair-major transposed shared ----
        const float4* xin4 = reinterpret_cast<const float4*>(xin + (size_t)chunk * KT * CH);
        #pragma unroll
        for (int j = 0; j < (KT * CH / 4) / THREADS; j++) {   // 8 iters
            int idx4 = j * THREADS + t;           // 0..2047
            float4 v = xin4[idx4];
            int k  = idx4 >> 2;                   // 0..511
            int c4 = idx4 & 3;                    // channel group (4 channels)
            *reinterpret_cast<float2*>(&sxp[(2 * c4    ) * RS + 2 * k]) = make_float2(v.x, v.y);
            *reinterpret_cast<float2*>(&sxp[(2 * c4 + 1) * RS + 2 * k]) = make_float2(v.z, v.w);
        }
        __syncthreads();

        // ---- main FMA loop: lanes cover k with stride 2, 64 k per warp-iter ----
        #pragma unroll 4
        for (int it = 0; it < KT / 64; ++it) {    // 8 iters
            int kloc = it * 64 + lane * 2;
            int kk = chunk * KT + kloc;

            unsigned long long llv[RPW][2];
            #pragma unroll
            for (int r = 0; r < RPW; r++) {
                float2 lv = *reinterpret_cast<const float2*>(Lr + (size_t)r * NN + kk);
                llv[r][0] = f2_pack(lv.x, lv.x);
                llv[r][1] = f2_pack(lv.y, lv.y);
            }
            #pragma unroll
            for (int c2 = 0; c2 < 8; c2++) {
                ulonglong2 q = *reinterpret_cast<const ulonglong2*>(&sxp[c2 * RS + 2 * kloc]);
                #pragma unroll
                for (int r = 0; r < RPW; r++) {
                    acc2[r][c2] = f2_fma(llv[r][0], q.x, acc2[r][c2]);  // k
                    acc2[r][c2] = f2_fma(llv[r][1], q.y, acc2[r][c2]);  // k+1
                }
            }
        }
        __syncthreads();
    }

    // ---- warp butterfly reduction: every lane ends with full y[4][16] ----
    float y[RPW][CH];
    #pragma unroll
    for (int r = 0; r < RPW; r++) {
        #pragma unroll
        for (int c2 = 0; c2 < 8; c2++) {
            unsigned long long v = acc2[r][c2];
            #pragma unroll
            for (int off = 16; off > 0; off >>= 1)
                v = f2_add(v, __shfl_xor_sync(0xffffffffu, v, off, 32));
            f2_unpack(v, y[r][2 * c2], y[r][2 * c2 + 1]);
        }
    }

    // ---- epilogue: each lane produces 2 of the 64 (row, channel) outputs ----
    #pragma unroll
    for (int h = 0; h < 2; ++h) {
        int o = lane + h * 32;
        int r = o >> 4;
        int c = o & 15;
        float s = 0.f;
        #pragma unroll
        for (int j = 0; j < CH; j++) s += y[r][j] * sW[j * CH + c];
        s = fmaxf(s, 0.f);                       // relu(y @ Wp)
        size_t gi = (size_t)(rowbase + r) * CH + c;
        if (!FINAL) {
            acc[gi] += s;
            xout[gi] = y[r][c];                  // raw L^p x for next pass
        } else {
            outp[gi] = fmaxf(acc[gi] + s, 0.f);  // final relu
        }
    }
}

extern "C" void kernel_launch(void* const* d_in, const int* in_sizes, int n_in,
                              void* d_out, int out_size) {
    const float* x = (const float*)d_in[0];   // [8192, 16]
    const float* L = (const float*)d_in[1];   // [8192, 8192]
    const float* W = (const float*)d_in[2];   // [5, 16, 16]
    float* out = (float*)d_out;

    void *p0, *p1, *pa;
    cudaGetSymbolAddress(&p0, g_xbuf0);
    cudaGetSymbolAddress(&p1, g_xbuf1);
    cudaGetSymbolAddress(&pa, g_acc);
    float* xb0 = (float*)p0;
    float* xb1 = (float*)p1;
    float* acc = (float*)pa;

    k_init<<<NN / THREADS, THREADS>>>(x, W, acc);                                   // acc = relu(x@W0)
    k_pass<false><<<NCTA, THREADS>>>(L, x,   xb0, W + 1 * 256, acc, nullptr);       // p=1
    k_pass<false><<<NCTA, THREADS>>>(L, xb0, xb1, W + 2 * 256, acc, nullptr);       // p=2
    k_pass<false><<<NCTA, THREADS>>>(L, xb1, xb0, W + 3 * 256, acc, nullptr);       // p=3
    k_pass<true ><<<NCTA, THREADS>>>(L, xb0, nullptr, W + 4 * 256, acc, out);       // p=4 + final relu
}

// round 3
// speedup vs baseline: 1.0042x; 1.0042x over previous
#include <cuda_runtime.h>
#include <cstdint>

// Problem constants
#define NN      8192
#define CH      16
#define KT      512            // k-chunk staged in shared
#define RS      1028           // padded row stride (float words) per channel-pair row (2*KT + 4)
#define RPW     4              // rows per warp
#define WPC     8              // warps per CTA
#define RPC     32             // rows per CTA
#define THREADS 256
#define NCTA    (NN / RPC)     // 256

// Scratch (no allocation allowed): ping-pong xp buffers + accumulator
__device__ __align__(128) float g_xbuf0[NN * CH];
__device__ __align__(128) float g_xbuf1[NN * CH];
__device__ __align__(128) float g_acc[NN * CH];

// ---------------- packed f32x2 helpers ----------------
__device__ __forceinline__ unsigned long long f2_fma(unsigned long long a,
                                                     unsigned long long b,
                                                     unsigned long long c) {
    unsigned long long d;
    asm("fma.rn.f32x2 %0, %1, %2, %3;" : "=l"(d) : "l"(a), "l"(b), "l"(c));
    return d;
}
__device__ __forceinline__ unsigned long long f2_add(unsigned long long a,
                                                     unsigned long long b) {
    unsigned long long d;
    asm("add.rn.f32x2 %0, %1, %2;" : "=l"(d) : "l"(a), "l"(b));
    return d;
}
__device__ __forceinline__ unsigned long long f2_pack(float lo, float hi) {
    unsigned long long d;
    asm("mov.b64 %0, {%1, %2};" : "=l"(d) : "f"(lo), "f"(hi));
    return d;
}
__device__ __forceinline__ void f2_unpack(unsigned long long v, float& lo, float& hi) {
    asm("mov.b64 {%0, %1}, %2;" : "=f"(lo), "=f"(hi) : "l"(v));
}

// ---------------- kernel 0: acc = relu(x @ W0) ----------------
__global__ void k_init(const float* __restrict__ x,
                       const float* __restrict__ W,   // W0: [16][16]
                       float* __restrict__ acc) {
    __shared__ float sW[CH * CH];
    int t = threadIdx.x;
    sW[t] = W[t];
    __syncthreads();

    int row = blockIdx.x * blockDim.x + t;   // grid = 32 blocks of 256
    const float4* xr4 = reinterpret_cast<const float4*>(x + (size_t)row * CH);
    float xr[CH];
    float4 v0 = xr4[0], v1 = xr4[1], v2 = xr4[2], v3 = xr4[3];
    xr[0]=v0.x; xr[1]=v0.y; xr[2]=v0.z; xr[3]=v0.w;
    xr[4]=v1.x; xr[5]=v1.y; xr[6]=v1.z; xr[7]=v1.w;
    xr[8]=v2.x; xr[9]=v2.y; xr[10]=v2.z; xr[11]=v2.w;
    xr[12]=v3.x; xr[13]=v3.y; xr[14]=v3.z; xr[15]=v3.w;

    float o[CH];
    #pragma unroll
    for (int c = 0; c < CH; c++) o[c] = 0.f;
    #pragma unroll
    for (int j = 0; j < CH; j++) {
        #pragma unroll
        for (int c = 0; c < CH; c++) o[c] += xr[j] * sW[j * CH + c];
    }
    float* ar = acc + (size_t)row * CH;
    #pragma unroll
    for (int c = 0; c < CH; c++) ar[c] = fmaxf(o[c], 0.f);
}

// ---------------- pass kernel: y = L @ xin ; acc += relu(y @ Wp) ; xout = y ----------------
// FINAL: out = relu(acc + relu(y @ Wp)), no xout write.
template <bool FINAL>
__global__ __launch_bounds__(THREADS, 2)
void k_pass(const float* __restrict__ L,
            const float* __restrict__ xin,
            float* __restrict__ xout,
            const float* __restrict__ W,      // Wp: [16][16]
            float* __restrict__ acc,
            float* __restrict__ outp) {
    // Channel-pair-major transposed xp chunk: sxp[c2*RS + 2*k + j] = xp[k][2*c2 + j]
    __shared__ __align__(16) float sxp[8 * RS];
    __shared__ float sW[CH * CH];

    int t = threadIdx.x;
    sW[t] = W[t];

    int warp = t >> 5;
    int lane = t & 31;
    int rowbase = blockIdx.x * RPC + warp * RPW;
    const float* Lr = L + (size_t)rowbase * NN;

    unsigned long long acc2[RPW][8];
    #pragma unroll
    for (int r = 0; r < RPW; r++)
        #pragma unroll
        for (int c2 = 0; c2 < 8; c2++) acc2[r][c2] = 0ull;

    for (int chunk = 0; chunk < NN / KT; ++chunk) {   // 16 chunks
        // ---- stage xp[chunk*KT .. +KT)[16] into pair-major transposed shared ----
        const float4* xin4 = reinterpret_cast<const float4*>(xin + (size_t)chunk * KT * CH);
        #pragma unroll
        for (int j = 0; j < (KT * CH / 4) / THREADS; j++) {   // 8 iters
            int idx4 = j * THREADS + t;           // 0..2047
            float4 v = xin4[idx4];
            int k  = idx4 >> 2;                   // 0..511
            int c4 = idx4 & 3;                    // channel group (4 channels)
            *reinterpret_cast<float2*>(&sxp[(2 * c4    ) * RS + 2 * k]) = make_float2(v.x, v.y);
            *reinterpret_cast<float2*>(&sxp[(2 * c4 + 1) * RS + 2 * k]) = make_float2(v.z, v.w);
        }
        __syncthreads();

        // ---- main FMA loop: lanes cover k with stride 2, 64 k per warp-iter ----
        #pragma unroll 4
        for (int it = 0; it < KT / 64; ++it) {    // 8 iters
            int kloc = it * 64 + lane * 2;
            int kk = chunk * KT + kloc;

            unsigned long long llv[RPW][2];
            #pragma unroll
            for (int r = 0; r < RPW; r++) {
                float2 lv = *reinterpret_cast<const float2*>(Lr + (size_t)r * NN + kk);
                llv[r][0] = f2_pack(lv.x, lv.x);
                llv[r][1] = f2_pack(lv.y, lv.y);
            }
            #pragma unroll
            for (int c2 = 0; c2 < 8; c2++) {
                ulonglong2 q = *reinterpret_cast<const ulonglong2*>(&sxp[c2 * RS + 2 * kloc]);
                #pragma unroll
                for (int r = 0; r < RPW; r++) {
                    acc2[r][c2] = f2_fma(llv[r][0], q.x, acc2[r][c2]);  // k
                    acc2[r][c2] = f2_fma(llv[r][1], q.y, acc2[r][c2]);  // k+1
                }
            }
        }
        __syncthreads();
    }

    // ---- warp butterfly reduction: every lane ends with full y[4][16] ----
    float y[RPW][CH];
    #pragma unroll
    for (int r = 0; r < RPW; r++) {
        #pragma unroll
        for (int c2 = 0; c2 < 8; c2++) {
            unsigned long long v = acc2[r][c2];
            #pragma unroll
            for (int off = 16; off > 0; off >>= 1)
                v = f2_add(v, __shfl_xor_sync(0xffffffffu, v, off, 32));
            f2_unpack(v, y[r][2 * c2], y[r][2 * c2 + 1]);
        }
    }

    // ---- epilogue: each lane produces 2 of the 64 (row, channel) outputs ----
    #pragma unroll
    for (int h = 0; h < 2; ++h) {
        int o = lane + h * 32;
        int r = o >> 4;
        int c = o & 15;
        float s = 0.f;
        #pragma unroll
        for (int j = 0; j < CH; j++) s += y[r][j] * sW[j * CH + c];
        s = fmaxf(s, 0.f);                       // relu(y @ Wp)
        size_t gi = (size_t)(rowbase + r) * CH + c;
        if (!FINAL) {
            acc[gi] += s;
            xout[gi] = y[r][c];                  // raw L^p x for next pass
        } else {
            outp[gi] = fmaxf(acc[gi] + s, 0.f);  // final relu
        }
    }
}

extern "C" void kernel_launch(void* const* d_in, const int* in_sizes, int n_in,
                              void* d_out, int out_size) {
    const float* x = (const float*)d_in[0];   // [8192, 16]
    const float* L = (const float*)d_in[1];   // [8192, 8192]
    const float* W = (const float*)d_in[2];   // [5, 16, 16]
    float* out = (float*)d_out;

    void *p0, *p1, *pa;
    cudaGetSymbolAddress(&p0, g_xbuf0);
    cudaGetSymbolAddress(&p1, g_xbuf1);
    cudaGetSymbolAddress(&pa, g_acc);
    float* xb0 = (float*)p0;
    float* xb1 = (float*)p1;
    float* acc = (float*)pa;

    k_init<<<NN / THREADS, THREADS>>>(x, W, acc);                                   // acc = relu(x@W0)
    k_pass<false><<<NCTA, THREADS>>>(L, x,   xb0, W + 1 * 256, acc, nullptr);       // p=1
    k_pass<false><<<NCTA, THREADS>>>(L, xb0, xb1, W + 2 * 256, acc, nullptr);       // p=2
    k_pass<false><<<NCTA, THREADS>>>(L, xb1, xb0, W + 3 * 256, acc, nullptr);       // p=3
    k_pass<true ><<<NCTA, THREADS>>>(L, xb0, nullptr, W + 4 * 256, acc, out);       // p=4 + final relu
}